// round 10
// baseline (speedup 1.0000x reference)
#include <cuda_runtime.h>
#include <math.h>

#define FULL 0xffffffffu
#define D 64
#define HID 32
#define TRAJ_LEN 11
#define MAX_INNER 64

// Tsit5 tableau
#define A21f 0.161f
#define A31f -0.008480655492356989f
#define A32f 0.335480655492357f
#define A41f 2.8971530571054935f
#define A42f -6.359448489975075f
#define A43f 4.3622954328695815f
#define A51f 5.325864828439257f
#define A52f -11.748883564062828f
#define A53f 7.4955393428898365f
#define A54f -0.09249506636175525f
#define A61f 5.86145544294642f
#define A62f -12.92096931784711f
#define A63f 8.159367898576159f
#define A64f -0.071584973281401f
#define A65f -0.028269050394068383f
#define B1f 0.09646076681806523f
#define B2f 0.01f
#define B3f 0.4798896504144996f
#define B4f 1.379008574103742f
#define B5f -3.290069515436081f
#define B6f 2.324710524099774f
#define E1f -0.00178001105222577714f
#define E2f -0.0008164344596567469f
#define E3f 0.007880878010261995f
#define E4f -0.1447110071732629f
#define E5f 0.5823571654525552f
#define E6f -0.45808210592918697f
#define E7f 0.015151515151515152f

struct V8 { float v[8]; };

__device__ __forceinline__ float softplus_f(float x) {
    float e = __expf(-fabsf(x));
    return fmaxf(x, 0.0f) + __logf(1.0f + e);
}

// Warp = 4 trajectories (groups of 8 lanes). Lane (g, c): holds state comps
// c*8+m; computes hidden units c*4+u and output comps c*8+m.
// Weight smem layouts (built once per block):
//   sW1[j*8+c]   = {W1[c*4+u][j]}_{u=0..3}   j<64  (128B consecutive per j)
//   sW2[j*8+c]   = {W2[c*4+u][j]}            j<32
//   sW3lo[j*8+c] = {W3[c*8+u][j]}_{u=0..3}   j<32
//   sW3hi[j*8+c] = {W3[c*8+4+u][j]}          j<32
// All reads: 8 distinct consecutive float4 x 4-way group broadcast -> 1 wavefront.
__device__ __forceinline__ void mlp_eval(
    const float4* __restrict__ sW1, const float4* __restrict__ sW2,
    const float4* __restrict__ sW3lo, const float4* __restrict__ sW3hi,
    const float4& bz1, const float4& bz2, const V8& bz3,
    int c, const V8& y, V8& o)
{
    // layer 1: 4 hidden units per lane
    float a0 = bz1.x, a1 = bz1.y, a2 = bz1.z, a3 = bz1.w;
    #pragma unroll
    for (int j = 0; j < 64; j++) {
        float yj = __shfl_sync(FULL, y.v[j & 7], j >> 3, 8);
        float4 w = sW1[j * 8 + c];
        a0 = fmaf(w.x, yj, a0);
        a1 = fmaf(w.y, yj, a1);
        a2 = fmaf(w.z, yj, a2);
        a3 = fmaf(w.w, yj, a3);
    }
    float hh[4];
    hh[0] = softplus_f(a0); hh[1] = softplus_f(a1);
    hh[2] = softplus_f(a2); hh[3] = softplus_f(a3);

    // layer 2
    float c0 = bz2.x, c1 = bz2.y, c2 = bz2.z, c3 = bz2.w;
    #pragma unroll
    for (int j = 0; j < 32; j++) {
        float hj = __shfl_sync(FULL, hh[j & 3], j >> 2, 8);
        float4 w = sW2[j * 8 + c];
        c0 = fmaf(w.x, hj, c0);
        c1 = fmaf(w.y, hj, c1);
        c2 = fmaf(w.z, hj, c2);
        c3 = fmaf(w.w, hj, c3);
    }
    float g2[4];
    g2[0] = softplus_f(c0); g2[1] = softplus_f(c1);
    g2[2] = softplus_f(c2); g2[3] = softplus_f(c3);

    // layer 3: 8 output comps per lane
    float o0 = bz3.v[0], o1 = bz3.v[1], o2 = bz3.v[2], o3 = bz3.v[3];
    float o4 = bz3.v[4], o5 = bz3.v[5], o6 = bz3.v[6], o7 = bz3.v[7];
    #pragma unroll
    for (int j = 0; j < 32; j++) {
        float hj = __shfl_sync(FULL, g2[j & 3], j >> 2, 8);
        float4 wl = sW3lo[j * 8 + c];
        float4 wh = sW3hi[j * 8 + c];
        o0 = fmaf(wl.x, hj, o0); o1 = fmaf(wl.y, hj, o1);
        o2 = fmaf(wl.z, hj, o2); o3 = fmaf(wl.w, hj, o3);
        o4 = fmaf(wh.x, hj, o4); o5 = fmaf(wh.y, hj, o5);
        o6 = fmaf(wh.z, hj, o6); o7 = fmaf(wh.w, hj, o7);
    }
    o.v[0] = o0; o.v[1] = o1; o.v[2] = o2; o.v[3] = o3;
    o.v[4] = o4; o.v[5] = o5; o.v[6] = o6; o.v[7] = o7;
}

__global__ void __launch_bounds__(64)
ode_tsit5_kernel(
    const float* __restrict__ x0,
    const float* __restrict__ W1, const float* __restrict__ b1,
    const float* __restrict__ W2, const float* __restrict__ b2,
    const float* __restrict__ W3, const float* __restrict__ b3,
    const int* __restrict__ Tp,
    float* __restrict__ out, int nb, int out_size)
{
    __shared__ float4 sW1[64 * 8];
    __shared__ float4 sW2[32 * 8];
    __shared__ float4 sW3lo[32 * 8];
    __shared__ float4 sW3hi[32 * 8];

    int tid = threadIdx.x;
    for (int idx = tid; idx < 64 * 8; idx += 64) {
        int j = idx >> 3, cc = idx & 7;
        sW1[idx] = make_float4(W1[(cc * 4 + 0) * 64 + j], W1[(cc * 4 + 1) * 64 + j],
                               W1[(cc * 4 + 2) * 64 + j], W1[(cc * 4 + 3) * 64 + j]);
    }
    for (int idx = tid; idx < 32 * 8; idx += 64) {
        int j = idx >> 3, cc = idx & 7;
        sW2[idx] = make_float4(W2[(cc * 4 + 0) * 32 + j], W2[(cc * 4 + 1) * 32 + j],
                               W2[(cc * 4 + 2) * 32 + j], W2[(cc * 4 + 3) * 32 + j]);
        sW3lo[idx] = make_float4(W3[(cc * 8 + 0) * 32 + j], W3[(cc * 8 + 1) * 32 + j],
                                 W3[(cc * 8 + 2) * 32 + j], W3[(cc * 8 + 3) * 32 + j]);
        sW3hi[idx] = make_float4(W3[(cc * 8 + 4) * 32 + j], W3[(cc * 8 + 5) * 32 + j],
                                 W3[(cc * 8 + 6) * 32 + j], W3[(cc * 8 + 7) * 32 + j]);
    }
    __syncthreads();

    int gwarp = (int)((blockIdx.x * 64 + tid) >> 5);
    int lane = tid & 31;
    int g = lane >> 3;      // group within warp = trajectory slot
    int c = lane & 7;       // sub-lane within group
    int traj = gwarp * 4 + g;
    bool valid = traj < nb;
    int trajc = valid ? traj : (nb - 1);

    // per-lane biases (replicated across groups)
    float4 bz1 = make_float4(b1[c * 4 + 0], b1[c * 4 + 1], b1[c * 4 + 2], b1[c * 4 + 3]);
    float4 bz2 = make_float4(b2[c * 4 + 0], b2[c * 4 + 1], b2[c * 4 + 2], b2[c * 4 + 3]);
    V8 bz3;
    #pragma unroll
    for (int m = 0; m < 8; m++) bz3.v[m] = b3[c * 8 + m];

    // T may arrive as int32 or float32 bits; disambiguate heuristically.
    int ti = *Tp;
    float Tf = (ti > 0 && ti < 1000000) ? (float)ti : __int_as_float(ti);
    float tstep = Tf / (float)(TRAJ_LEN - 1);

    V8 y;
    {
        const float4* src = (const float4*)(x0 + (size_t)trajc * D + c * 8);
        float4 lo = src[0], hi = src[1];
        y.v[0] = lo.x; y.v[1] = lo.y; y.v[2] = lo.z; y.v[3] = lo.w;
        y.v[4] = hi.x; y.v[5] = hi.y; y.v[6] = hi.z; y.v[7] = hi.w;
    }

    size_t obase = ((size_t)trajc * TRAJ_LEN) * D + c * 8;
    if (valid) {
        float4* dst = (float4*)(out + obase);
        dst[0] = make_float4(y.v[0], y.v[1], y.v[2], y.v[3]);
        dst[1] = make_float4(y.v[4], y.v[5], y.v[6], y.v[7]);
    }

    float t = 0.0f;
    float dt = 1e-3f;
    int n = 0;

    // FSAL k1 cache (exact: accepted -> f(y_new)==k7 bitwise; rejected -> y unchanged)
    V8 k1;
    mlp_eval(sW1, sW2, sW3lo, sW3hi, bz1, bz2, bz3, c, y, k1);

    for (int s = 1; s < TRAJ_LEN; s++) {
        float tt = tstep * (float)s;
        for (int it = 0; it < MAX_INNER; it++) {
            float remaining = tt - t;
            bool done = (remaining <= 1e-12f);
            if (__all_sync(FULL, done)) break;   // all 4 groups done -> masked iters are no-ops
            float h = fminf(dt, fmaxf(remaining, 0.0f));

            V8 z, k2, k3, k4, k5, k6, y5, k7;

            #pragma unroll
            for (int m = 0; m < 8; m++)
                z.v[m] = fmaf(h, A21f * k1.v[m], y.v[m]);
            mlp_eval(sW1, sW2, sW3lo, sW3hi, bz1, bz2, bz3, c, z, k2);

            #pragma unroll
            for (int m = 0; m < 8; m++)
                z.v[m] = fmaf(h, fmaf(A32f, k2.v[m], A31f * k1.v[m]), y.v[m]);
            mlp_eval(sW1, sW2, sW3lo, sW3hi, bz1, bz2, bz3, c, z, k3);

            #pragma unroll
            for (int m = 0; m < 8; m++)
                z.v[m] = fmaf(h, fmaf(A43f, k3.v[m], fmaf(A42f, k2.v[m], A41f * k1.v[m])), y.v[m]);
            mlp_eval(sW1, sW2, sW3lo, sW3hi, bz1, bz2, bz3, c, z, k4);

            #pragma unroll
            for (int m = 0; m < 8; m++)
                z.v[m] = fmaf(h, fmaf(A54f, k4.v[m], fmaf(A53f, k3.v[m], fmaf(A52f, k2.v[m], A51f * k1.v[m]))), y.v[m]);
            mlp_eval(sW1, sW2, sW3lo, sW3hi, bz1, bz2, bz3, c, z, k5);

            #pragma unroll
            for (int m = 0; m < 8; m++)
                z.v[m] = fmaf(h, fmaf(A65f, k5.v[m], fmaf(A64f, k4.v[m], fmaf(A63f, k3.v[m], fmaf(A62f, k2.v[m], A61f * k1.v[m])))), y.v[m]);
            mlp_eval(sW1, sW2, sW3lo, sW3hi, bz1, bz2, bz3, c, z, k6);

            #pragma unroll
            for (int m = 0; m < 8; m++)
                y5.v[m] = fmaf(h, fmaf(B6f, k6.v[m], fmaf(B5f, k5.v[m], fmaf(B4f, k4.v[m],
                           fmaf(B3f, k3.v[m], fmaf(B2f, k2.v[m], B1f * k1.v[m]))))), y.v[m]);
            mlp_eval(sW1, sW2, sW3lo, sW3hi, bz1, bz2, bz3, c, y5, k7);

            float ss = 0.0f;
            #pragma unroll
            for (int m = 0; m < 8; m++) {
                float err = h * fmaf(E7f, k7.v[m], fmaf(E6f, k6.v[m], fmaf(E5f, k5.v[m],
                            fmaf(E4f, k4.v[m], fmaf(E3f, k3.v[m], fmaf(E2f, k2.v[m], E1f * k1.v[m]))))));
                float sc = fmaf(1e-3f, fmaxf(fabsf(y.v[m]), fabsf(y5.v[m])), 1e-6f);
                float e = err / sc;
                ss = fmaf(e, e, ss);
            }
            // reduce across the 8 lanes of this group (xor 1/2/4 stays in group)
            ss += __shfl_xor_sync(FULL, ss, 1);
            ss += __shfl_xor_sync(FULL, ss, 2);
            ss += __shfl_xor_sync(FULL, ss, 4);
            float enorm = fmaxf(sqrtf(ss * (1.0f / 64.0f)), 1e-10f);

            bool accept = (enorm <= 1.0f);
            float fac = fminf(fmaxf(0.9f * __powf(enorm, -0.2f), 0.1f), 5.0f);
            bool step_ok = accept && !done;

            if (step_ok) {
                t = t + h;
                #pragma unroll
                for (int m = 0; m < 8; m++) { y.v[m] = y5.v[m]; k1.v[m] = k7.v[m]; }
            }
            if (!done) {
                dt = fmaxf(h * fac, 1e-8f);
                n++;
            }
        }
        if (valid) {
            float4* dst = (float4*)(out + obase + (size_t)s * D);
            dst[0] = make_float4(y.v[0], y.v[1], y.v[2], y.v[3]);
            dst[1] = make_float4(y.v[4], y.v[5], y.v[6], y.v[7]);
        }
    }

    // second output: sum of attempt counts (integer-exact in f32, order-free)
    int traj_elems = nb * TRAJ_LEN * D;
    if (valid && c == 0 && out_size > traj_elems) {
        atomicAdd(&out[traj_elems], (float)n);
    }
}

extern "C" void kernel_launch(void* const* d_in, const int* in_sizes, int n_in,
                              void* d_out, int out_size) {
    const float* x0 = (const float*)d_in[0];
    const float* W1 = (const float*)d_in[1];
    const float* b1 = (const float*)d_in[2];
    const float* W2 = (const float*)d_in[3];
    const float* b2 = (const float*)d_in[4];
    const float* W3 = (const float*)d_in[5];
    const float* b3 = (const float*)d_in[6];
    const int*   Tp = (const int*)d_in[7];
    float* out = (float*)d_out;

    int nb = in_sizes[0] / D;                 // 4096 trajectories
    int traj_elems = nb * TRAJ_LEN * D;

    if (out_size > traj_elems) {
        cudaMemsetAsync((char*)d_out + (size_t)traj_elems * sizeof(float), 0,
                        (size_t)(out_size - traj_elems) * sizeof(float), 0);
    }

    int warps = (nb + 3) / 4;                 // 4 trajectories per warp
    int threads = 64;                          // 2 warps per block (shared weight copy)
    int blocks = (warps * 32 + threads - 1) / threads;
    ode_tsit5_kernel<<<blocks, threads>>>(x0, W1, b1, W2, b2, W3, b3, Tp,
                                          out, nb, out_size);
}